// round 1
// baseline (speedup 1.0000x reference)
#include <cuda_runtime.h>

#define N_NODES 100000
#define N_EDGES 1600000
#define NODE_DIM 128
#define EDGE_DIM 48
#define IN_DIM 176
#define HID 64
#define LN_EPS 1e-5f

// ---------------- scratch (static device globals; no runtime allocation) ---
__device__ int   g_deg[N_NODES];
__device__ int   g_off[N_NODES + 1];
__device__ int   g_cursor[N_NODES];
__device__ int   g_csr[N_EDGES];
__device__ int   g_partial[128];
__device__ int   g_base[128];
__device__ float g_agg[(size_t)N_NODES * EDGE_DIM];

typedef unsigned long long ull;

// ---------------- packed f32x2 helpers (Blackwell sm_100+) -----------------
__device__ __forceinline__ ull ffma2(ull a, ull b, ull c) {
    ull d;
    asm("fma.rn.f32x2 %0, %1, %2, %3;" : "=l"(d) : "l"(a), "l"(b), "l"(c));
    return d;
}
__device__ __forceinline__ ull fadd2(ull a, ull b) {
    ull d;
    asm("add.rn.f32x2 %0, %1, %2;" : "=l"(d) : "l"(a), "l"(b));
    return d;
}
__device__ __forceinline__ ull fmul2(ull a, ull b) {
    ull d;
    asm("mul.rn.f32x2 %0, %1, %2;" : "=l"(d) : "l"(a), "l"(b));
    return d;
}
__device__ __forceinline__ ull dup2(float x) {
    ull d; unsigned u = __float_as_uint(x);
    asm("mov.b64 %0, {%1, %1};" : "=l"(d) : "r"(u));
    return d;
}
__device__ __forceinline__ ull pack2(float lo, float hi) {
    ull d;
    asm("mov.b64 %0, {%1, %2};" : "=l"(d)
        : "r"(__float_as_uint(lo)), "r"(__float_as_uint(hi)));
    return d;
}
__device__ __forceinline__ void unpack2(ull a, float& lo, float& hi) {
    unsigned l, h;
    asm("mov.b64 {%0, %1}, %2;" : "=r"(l), "=r"(h) : "l"(a));
    lo = __uint_as_float(l);
    hi = __uint_as_float(h);
}

// ---------------- CSR build kernels ----------------------------------------
__global__ void k_zero() {
    int i = blockIdx.x * blockDim.x + threadIdx.x;
    if (i < N_NODES) g_deg[i] = 0;
}

__global__ void k_hist(const int* __restrict__ recv) {
    int e = blockIdx.x * blockDim.x + threadIdx.x;
    if (e < N_EDGES) atomicAdd(&g_deg[recv[e]], 1);
}

__global__ void k_partial() {
    int i = blockIdx.x * 1024 + threadIdx.x;
    int v = (i < N_NODES) ? g_deg[i] : 0;
    int lane = threadIdx.x & 31, w = threadIdx.x >> 5;
    #pragma unroll
    for (int o = 16; o > 0; o >>= 1) v += __shfl_down_sync(0xffffffffu, v, o);
    __shared__ int ws[32];
    if (lane == 0) ws[w] = v;
    __syncthreads();
    if (w == 0) {
        int s = ws[lane];
        #pragma unroll
        for (int o = 16; o > 0; o >>= 1) s += __shfl_down_sync(0xffffffffu, s, o);
        if (lane == 0) g_partial[blockIdx.x] = s;
    }
}

__global__ void k_scanp() {
    __shared__ int sh[128];
    int t = threadIdx.x;
    int v = (t < 98) ? g_partial[t] : 0;
    sh[t] = v;
    __syncthreads();
    for (int o = 1; o < 128; o <<= 1) {
        int a = 0;
        if (t >= o) a = sh[t - o];
        __syncthreads();
        sh[t] += a;
        __syncthreads();
    }
    if (t < 98) g_base[t] = sh[t] - v;       // exclusive block base
    if (t == 127) g_off[N_NODES] = sh[127];  // total == N_EDGES
}

__global__ void k_off() {
    int i = blockIdx.x * 1024 + threadIdx.x;
    int v = (i < N_NODES) ? g_deg[i] : 0;
    int lane = threadIdx.x & 31, w = threadIdx.x >> 5;
    int incl = v;
    #pragma unroll
    for (int o = 1; o < 32; o <<= 1) {
        int a = __shfl_up_sync(0xffffffffu, incl, o);
        if (lane >= o) incl += a;
    }
    __shared__ int wsum[32], woff[32];
    if (lane == 31) wsum[w] = incl;
    __syncthreads();
    if (w == 0) {
        int t = wsum[lane];
        int ti = t;
        #pragma unroll
        for (int o = 1; o < 32; o <<= 1) {
            int a = __shfl_up_sync(0xffffffffu, ti, o);
            if (lane >= o) ti += a;
        }
        woff[lane] = ti - t;
    }
    __syncthreads();
    int excl = incl - v + woff[w] + g_base[blockIdx.x];
    if (i < N_NODES) {
        g_off[i] = excl;
        g_cursor[i] = excl;
    }
}

__global__ void k_fill(const int* __restrict__ recv) {
    int e = blockIdx.x * blockDim.x + threadIdx.x;
    if (e < N_EDGES) {
        int r = recv[e];
        int p = atomicAdd(&g_cursor[r], 1);
        g_csr[p] = e;
    }
}

// ---------------- gather-mean: 4 threads per node, 48B contiguous each -----
__global__ void k_gather(const float* __restrict__ ef) {
    int gid = blockIdx.x * blockDim.x + threadIdx.x;
    int n = gid >> 2;
    if (n >= N_NODES) return;
    int sub = gid & 3;
    int s = g_off[n], e = g_off[n + 1];
    float4 a0 = make_float4(0.f, 0.f, 0.f, 0.f), a1 = a0, a2 = a0;
    const float4* ef4 = (const float4*)ef;
    int p = s;
    int eid = (p < e) ? g_csr[p] : 0;
    for (; p < e; p++) {
        int nxt = (p + 1 < e) ? g_csr[p + 1] : 0;   // prefetch next index
        const float4* row = ef4 + (size_t)eid * 12 + sub * 3;
        float4 r0 = row[0], r1 = row[1], r2 = row[2];
        a0.x += r0.x; a0.y += r0.y; a0.z += r0.z; a0.w += r0.w;
        a1.x += r1.x; a1.y += r1.y; a1.z += r1.z; a1.w += r1.w;
        a2.x += r2.x; a2.y += r2.y; a2.z += r2.z; a2.w += r2.w;
        eid = nxt;
    }
    int d = e - s;
    float sc = 1.0f / (float)(d > 0 ? d : 1);
    a0.x *= sc; a0.y *= sc; a0.z *= sc; a0.w *= sc;
    a1.x *= sc; a1.y *= sc; a1.z *= sc; a1.w *= sc;
    a2.x *= sc; a2.y *= sc; a2.z *= sc; a2.w *= sc;
    float4* o = (float4*)(g_agg + (size_t)n * 48 + sub * 12);
    o[0] = a0; o[1] = a1; o[2] = a2;
}

// ---------------- fused MLP + LayerNorm ------------------------------------
// Block: 256 threads, 128 nodes. thread t: cg=t&15 -> cols j0=4*cg,
// ng=t>>4 -> 8 nodes (4 node-pairs). Accumulators are f32x2 over node pairs.
// Shared x-tile is transposed [k][node] (pitch 132) so node pairs load as 64b.

#define XPITCH 132
#define SM_XT   0
#define SM_W1   (176 * XPITCH)                 // 23232
#define SM_W2   (SM_W1 + IN_DIM * HID)         // +11264
#define SM_W3   (SM_W2 + HID * HID)            // +4096
#define SM_HT   (SM_W3 + HID * HID)            // +4096
#define SM_V    (SM_HT + HID * XPITCH)         // +8448
#define SM_FLOATS (SM_V + 5 * HID)             // 51456 floats = 205824 B

template<int K>
__device__ __forceinline__ void gemm_acc(const float* __restrict__ sIn,
                                         const float* __restrict__ sW,
                                         int j0, int nb, ull acc[4][4]) {
    #pragma unroll 8
    for (int k = 0; k < K; k++) {
        const ulonglong2* xp = (const ulonglong2*)(sIn + k * XPITCH + nb);
        ulonglong2 xa = xp[0];      // pairs (n0,n1), (n2,n3)
        ulonglong2 xb = xp[1];      // pairs (n4,n5), (n6,n7)
        float4 w = *(const float4*)(sW + k * HID + j0);
        ull w0 = dup2(w.x), w1 = dup2(w.y), w2 = dup2(w.z), w3 = dup2(w.w);
        acc[0][0] = ffma2(xa.x, w0, acc[0][0]);
        acc[0][1] = ffma2(xa.x, w1, acc[0][1]);
        acc[0][2] = ffma2(xa.x, w2, acc[0][2]);
        acc[0][3] = ffma2(xa.x, w3, acc[0][3]);
        acc[1][0] = ffma2(xa.y, w0, acc[1][0]);
        acc[1][1] = ffma2(xa.y, w1, acc[1][1]);
        acc[1][2] = ffma2(xa.y, w2, acc[1][2]);
        acc[1][3] = ffma2(xa.y, w3, acc[1][3]);
        acc[2][0] = ffma2(xb.x, w0, acc[2][0]);
        acc[2][1] = ffma2(xb.x, w1, acc[2][1]);
        acc[2][2] = ffma2(xb.x, w2, acc[2][2]);
        acc[2][3] = ffma2(xb.x, w3, acc[2][3]);
        acc[3][0] = ffma2(xb.y, w0, acc[3][0]);
        acc[3][1] = ffma2(xb.y, w1, acc[3][1]);
        acc[3][2] = ffma2(xb.y, w2, acc[3][2]);
        acc[3][3] = ffma2(xb.y, w3, acc[3][3]);
    }
}

__device__ __forceinline__ void init_bias(const float* __restrict__ sB,
                                          int j0, ull acc[4][4]) {
    ull bd[4];
    #pragma unroll
    for (int c = 0; c < 4; c++) bd[c] = dup2(sB[j0 + c]);
    #pragma unroll
    for (int p = 0; p < 4; p++)
        #pragma unroll
        for (int c = 0; c < 4; c++) acc[p][c] = bd[c];
}

__global__ void __launch_bounds__(256, 1)
k_mlp(const float* __restrict__ nf,
      const float* __restrict__ W1, const float* __restrict__ b1,
      const float* __restrict__ W2, const float* __restrict__ b2,
      const float* __restrict__ W3, const float* __restrict__ b3,
      const float* __restrict__ gamma, const float* __restrict__ beta,
      float* __restrict__ out) {
    extern __shared__ float sm[];
    float* sXT = sm + SM_XT;
    float* sW1 = sm + SM_W1;
    float* sW2 = sm + SM_W2;
    float* sW3 = sm + SM_W3;
    float* sHT = sm + SM_HT;
    float* sV  = sm + SM_V;

    int tid = threadIdx.x;
    int n0 = blockIdx.x * 128;

    // stage weights / vectors (L2-resident, broadcast-friendly)
    for (int i = tid; i < IN_DIM * HID; i += 256) sW1[i] = W1[i];
    for (int i = tid; i < HID * HID; i += 256) { sW2[i] = W2[i]; sW3[i] = W3[i]; }
    if (tid < HID) {
        sV[tid]           = b1[tid];
        sV[HID + tid]     = b2[tid];
        sV[2 * HID + tid] = b3[tid];
        sV[3 * HID + tid] = gamma[tid];
        sV[4 * HID + tid] = beta[tid];
    }
    // node features -> transposed x tile (coalesced gmem reads)
    for (int i = tid; i < 128 * NODE_DIM; i += 256) {
        int n = i >> 7, k = i & 127;
        int gn = n0 + n;
        sXT[k * XPITCH + n] = (gn < N_NODES) ? nf[(size_t)gn * NODE_DIM + k] : 0.f;
    }
    // aggregated edge means -> rows 128..175
    for (int i = tid; i < 128 * EDGE_DIM; i += 256) {
        int n = i / EDGE_DIM, c = i - n * EDGE_DIM;
        int gn = n0 + n;
        sXT[(NODE_DIM + c) * XPITCH + n] =
            (gn < N_NODES) ? g_agg[(size_t)gn * EDGE_DIM + c] : 0.f;
    }
    __syncthreads();

    int cg = tid & 15, ng = tid >> 4;
    int j0 = cg * 4, nb = ng * 8;
    ull acc[4][4];

    // layer 1: [128 x 176] @ [176 x 64] + b1, relu -> sHT (transposed)
    init_bias(sV, j0, acc);
    gemm_acc<IN_DIM>(sXT, sW1, j0, nb, acc);
    #pragma unroll
    for (int p = 0; p < 4; p++)
        #pragma unroll
        for (int c = 0; c < 4; c++) {
            float lo, hi; unpack2(acc[p][c], lo, hi);
            *(ull*)(sHT + (j0 + c) * XPITCH + nb + 2 * p) =
                pack2(fmaxf(lo, 0.f), fmaxf(hi, 0.f));
        }
    __syncthreads();

    // layer 2: sHT @ W2 + b2, relu -> reuse sXT
    init_bias(sV + HID, j0, acc);
    gemm_acc<HID>(sHT, sW2, j0, nb, acc);
    #pragma unroll
    for (int p = 0; p < 4; p++)
        #pragma unroll
        for (int c = 0; c < 4; c++) {
            float lo, hi; unpack2(acc[p][c], lo, hi);
            *(ull*)(sXT + (j0 + c) * XPITCH + nb + 2 * p) =
                pack2(fmaxf(lo, 0.f), fmaxf(hi, 0.f));
        }
    __syncthreads();

    // layer 3: sXT(h2) @ W3 + b3 (no relu), then LayerNorm in registers
    init_bias(sV + 2 * HID, j0, acc);
    gemm_acc<HID>(sXT, sW3, j0, nb, acc);

    float gm[4], bt[4];
    #pragma unroll
    for (int c = 0; c < 4; c++) {
        gm[c] = sV[3 * HID + j0 + c];
        bt[c] = sV[4 * HID + j0 + c];
    }

    #pragma unroll
    for (int p = 0; p < 4; p++) {
        // mean over 64 cols: 4 local + 16-lane shuffle tree (both nodes packed)
        ull s = fadd2(fadd2(acc[p][0], acc[p][1]), fadd2(acc[p][2], acc[p][3]));
        #pragma unroll
        for (int m = 1; m < 16; m <<= 1)
            s = fadd2(s, __shfl_xor_sync(0xffffffffu, s, m));
        ull nmean = fmul2(s, dup2(-1.0f / 64.0f));
        ull d0 = fadd2(acc[p][0], nmean);
        ull d1 = fadd2(acc[p][1], nmean);
        ull d2 = fadd2(acc[p][2], nmean);
        ull d3 = fadd2(acc[p][3], nmean);
        ull q = fmul2(d0, d0);
        q = ffma2(d1, d1, q);
        q = ffma2(d2, d2, q);
        q = ffma2(d3, d3, q);
        #pragma unroll
        for (int m = 1; m < 16; m <<= 1)
            q = fadd2(q, __shfl_xor_sync(0xffffffffu, q, m));
        ull var = fmul2(q, dup2(1.0f / 64.0f));
        float vlo, vhi; unpack2(var, vlo, vhi);
        float rlo = rsqrtf(vlo + LN_EPS);
        float rhi = rsqrtf(vhi + LN_EPS);
        float l0, h0, l1, h1, l2, h2, l3, h3;
        unpack2(d0, l0, h0); unpack2(d1, l1, h1);
        unpack2(d2, l2, h2); unpack2(d3, l3, h3);
        int nA = n0 + nb + 2 * p, nB = nA + 1;
        if (nA < N_NODES) {
            float4 o;
            o.x = l0 * rlo * gm[0] + bt[0];
            o.y = l1 * rlo * gm[1] + bt[1];
            o.z = l2 * rlo * gm[2] + bt[2];
            o.w = l3 * rlo * gm[3] + bt[3];
            *(float4*)(out + (size_t)nA * HID + j0) = o;
        }
        if (nB < N_NODES) {
            float4 o;
            o.x = h0 * rhi * gm[0] + bt[0];
            o.y = h1 * rhi * gm[1] + bt[1];
            o.z = h2 * rhi * gm[2] + bt[2];
            o.w = h3 * rhi * gm[3] + bt[3];
            *(float4*)(out + (size_t)nB * HID + j0) = o;
        }
    }
}

// ---------------- launch ---------------------------------------------------
extern "C" void kernel_launch(void* const* d_in, const int* in_sizes, int n_in,
                              void* d_out, int out_size) {
    const float* nf = 0;
    const float* ef = 0;
    const float* W1 = 0;
    const int* recv = 0;
    const float* mats[2] = {0, 0};
    const float* vecs[5] = {0, 0, 0, 0, 0};
    int mi = 0, vi = 0;
    for (int i = 0; i < n_in; i++) {
        int s = in_sizes[i];
        const void* p = d_in[i];
        if (s == N_NODES * NODE_DIM) nf = (const float*)p;
        else if (s == N_EDGES * EDGE_DIM) ef = (const float*)p;
        else if (s == N_EDGES) recv = (const int*)p;
        else if (s == IN_DIM * HID) W1 = (const float*)p;
        else if (s == HID * HID) { if (mi < 2) mats[mi++] = (const float*)p; }
        else if (s == HID) { if (vi < 5) vecs[vi++] = (const float*)p; }
    }
    float* out = (float*)d_out;

    cudaFuncSetAttribute(k_mlp, cudaFuncAttributeMaxDynamicSharedMemorySize,
                         SM_FLOATS * (int)sizeof(float));

    k_zero<<<(N_NODES + 255) / 256, 256>>>();
    k_hist<<<(N_EDGES + 255) / 256, 256>>>(recv);
    k_partial<<<(N_NODES + 1023) / 1024, 1024>>>();
    k_scanp<<<1, 128>>>();
    k_off<<<(N_NODES + 1023) / 1024, 1024>>>();
    k_fill<<<(N_EDGES + 255) / 256, 256>>>(recv);
    k_gather<<<(N_NODES * 4 + 255) / 256, 256>>>(ef);
    k_mlp<<<(N_NODES + 127) / 128, 256, SM_FLOATS * (int)sizeof(float)>>>(
        nf, W1, vecs[0], mats[0], vecs[1], mats[1], vecs[2],
        vecs[3], vecs[4], out);
}

// round 2
// speedup vs baseline: 1.2093x; 1.2093x over previous
#include <cuda_runtime.h>

#define N_NODES 100000
#define N_EDGES 1600000
#define NODE_DIM 128
#define EDGE_DIM 48
#define IN_DIM 176
#define HID 64
#define LN_EPS 1e-5f
#define SCAN_BLOCKS 98
#define N_PAD 100352          /* 98 * 1024, also >= mlp grid coverage */
#define XP 132                /* transposed-tile pitch (floats) */

// ---------------- scratch (static device globals; no runtime allocation) ---
__device__ int   g_deg[N_NODES];
__device__ int   g_off[N_NODES + 1];
__device__ int   g_cursor[N_NODES];
__device__ int   g_csr[N_EDGES];
__device__ int   g_scanA[SCAN_BLOCKS];
__device__ float g_agg[(size_t)N_NODES * EDGE_DIM];
__device__ float g_pre[(size_t)N_PAD * HID];

typedef unsigned long long ull;

// ---------------- packed f32x2 helpers -------------------------------------
__device__ __forceinline__ ull ffma2(ull a, ull b, ull c) {
    ull d;
    asm("fma.rn.f32x2 %0, %1, %2, %3;" : "=l"(d) : "l"(a), "l"(b), "l"(c));
    return d;
}
__device__ __forceinline__ ull fadd2(ull a, ull b) {
    ull d;
    asm("add.rn.f32x2 %0, %1, %2;" : "=l"(d) : "l"(a), "l"(b));
    return d;
}
__device__ __forceinline__ ull fmul2(ull a, ull b) {
    ull d;
    asm("mul.rn.f32x2 %0, %1, %2;" : "=l"(d) : "l"(a), "l"(b));
    return d;
}
__device__ __forceinline__ ull dup2(float x) {
    ull d; unsigned u = __float_as_uint(x);
    asm("mov.b64 %0, {%1, %1};" : "=l"(d) : "r"(u));
    return d;
}
__device__ __forceinline__ ull pack2(float lo, float hi) {
    ull d;
    asm("mov.b64 %0, {%1, %2};" : "=l"(d)
        : "r"(__float_as_uint(lo)), "r"(__float_as_uint(hi)));
    return d;
}
__device__ __forceinline__ void unpack2(ull a, float& lo, float& hi) {
    unsigned l, h;
    asm("mov.b64 {%0, %1}, %2;" : "=r"(l), "=r"(h) : "l"(a));
    lo = __uint_as_float(l);
    hi = __uint_as_float(h);
}

// ---------------- CSR build ------------------------------------------------
__global__ void k_zero() {
    int i = blockIdx.x * blockDim.x + threadIdx.x;
    if (i < N_NODES) g_deg[i] = 0;
    if (i < SCAN_BLOCKS) g_scanA[i] = -1;
}

__global__ void k_hist4(const int4* __restrict__ recv4) {
    int i = blockIdx.x * blockDim.x + threadIdx.x;
    if (i < N_EDGES / 4) {
        int4 r = recv4[i];
        atomicAdd(&g_deg[r.x], 1);
        atomicAdd(&g_deg[r.y], 1);
        atomicAdd(&g_deg[r.z], 1);
        atomicAdd(&g_deg[r.w], 1);
    }
}

// single-kernel scan: 98 blocks, all SM-resident -> safe spin barrier
__global__ void k_offscan() {
    int tid = threadIdx.x;
    int i = blockIdx.x * 1024 + tid;
    int v = (i < N_NODES) ? g_deg[i] : 0;
    int lane = tid & 31, w = tid >> 5;
    int incl = v;
    #pragma unroll
    for (int o = 1; o < 32; o <<= 1) {
        int a = __shfl_up_sync(0xffffffffu, incl, o);
        if (lane >= o) incl += a;
    }
    __shared__ int wsum[32], woff[32], sAgg[SCAN_BLOCKS], sBase, sTotal;
    if (lane == 31) wsum[w] = incl;
    __syncthreads();
    if (w == 0) {
        int t = wsum[lane], ti = t;
        #pragma unroll
        for (int o = 1; o < 32; o <<= 1) {
            int a = __shfl_up_sync(0xffffffffu, ti, o);
            if (lane >= o) ti += a;
        }
        woff[lane] = ti - t;
        if (lane == 31) sTotal = ti;
    }
    __syncthreads();
    if (tid == 0)
        *((volatile int*)&g_scanA[blockIdx.x]) = sTotal;   // publish aggregate
    if (tid < SCAN_BLOCKS) {
        volatile int* p = (volatile int*)&g_scanA[tid];
        int a;
        while ((a = *p) == -1) { }
        sAgg[tid] = a;
    }
    __syncthreads();
    if (tid == 0) {
        int b = 0;
        for (int j = 0; j < blockIdx.x; j++) b += sAgg[j];
        sBase = b;
        if (blockIdx.x == 0) g_off[N_NODES] = N_EDGES;
    }
    __syncthreads();
    int excl = sBase + woff[w] + incl - v;
    if (i < N_NODES) { g_off[i] = excl; g_cursor[i] = excl; }
}

__global__ void k_fill4(const int4* __restrict__ recv4) {
    int i = blockIdx.x * blockDim.x + threadIdx.x;
    if (i < N_EDGES / 4) {
        int4 r = recv4[i];
        int e0 = i * 4;
        int p;
        p = atomicAdd(&g_cursor[r.x], 1); g_csr[p] = e0;
        p = atomicAdd(&g_cursor[r.y], 1); g_csr[p] = e0 + 1;
        p = atomicAdd(&g_cursor[r.z], 1); g_csr[p] = e0 + 2;
        p = atomicAdd(&g_cursor[r.w], 1); g_csr[p] = e0 + 3;
    }
}

// ---------------- gather-mean: warp per node, 8 edges x 4 lanes per batch --
__device__ __forceinline__ void red4(float4& a, int m) {
    a.x += __shfl_xor_sync(0xffffffffu, a.x, m);
    a.y += __shfl_xor_sync(0xffffffffu, a.y, m);
    a.z += __shfl_xor_sync(0xffffffffu, a.z, m);
    a.w += __shfl_xor_sync(0xffffffffu, a.w, m);
}

__global__ void k_gather(const float* __restrict__ ef) {
    int n = (blockIdx.x * blockDim.x + threadIdx.x) >> 5;
    if (n >= N_NODES) return;
    int lane = threadIdx.x & 31;
    int g = lane >> 2, sub = lane & 3;
    int s = g_off[n], e = g_off[n + 1];
    float4 a0 = make_float4(0.f, 0.f, 0.f, 0.f), a1 = a0, a2 = a0;
    const float4* ef4 = (const float4*)ef;
    for (int p = s + g; p < e; p += 8) {
        int eid = __ldg(&g_csr[p]);
        const float4* row = ef4 + (size_t)eid * 12 + sub * 3;
        float4 r0 = __ldcs(row), r1 = __ldcs(row + 1), r2 = __ldcs(row + 2);
        a0.x += r0.x; a0.y += r0.y; a0.z += r0.z; a0.w += r0.w;
        a1.x += r1.x; a1.y += r1.y; a1.z += r1.z; a1.w += r1.w;
        a2.x += r2.x; a2.y += r2.y; a2.z += r2.z; a2.w += r2.w;
    }
    #pragma unroll
    for (int m = 4; m <= 16; m <<= 1) { red4(a0, m); red4(a1, m); red4(a2, m); }
    if (lane < 4) {
        int d = e - s;
        float sc = 1.0f / (float)(d > 0 ? d : 1);
        a0.x *= sc; a0.y *= sc; a0.z *= sc; a0.w *= sc;
        a1.x *= sc; a1.y *= sc; a1.z *= sc; a1.w *= sc;
        a2.x *= sc; a2.y *= sc; a2.z *= sc; a2.w *= sc;
        float4* o = (float4*)(g_agg + (size_t)n * 48 + sub * 12);
        o[0] = a0; o[1] = a1; o[2] = a2;
    }
}

// ---------------- MLP core pieces ------------------------------------------
template<int K>
__device__ __forceinline__ void gemm_acc(const float* __restrict__ sIn,
                                         const float* __restrict__ sW,
                                         int j0, int nb, ull acc[4][4]) {
    #pragma unroll 8
    for (int k = 0; k < K; k++) {
        const ulonglong2* xp = (const ulonglong2*)(sIn + k * XP + nb);
        ulonglong2 xa = xp[0];
        ulonglong2 xb = xp[1];
        float4 w = *(const float4*)(sW + k * HID + j0);
        ull w0 = dup2(w.x), w1 = dup2(w.y), w2 = dup2(w.z), w3 = dup2(w.w);
        acc[0][0] = ffma2(xa.x, w0, acc[0][0]);
        acc[0][1] = ffma2(xa.x, w1, acc[0][1]);
        acc[0][2] = ffma2(xa.x, w2, acc[0][2]);
        acc[0][3] = ffma2(xa.x, w3, acc[0][3]);
        acc[1][0] = ffma2(xa.y, w0, acc[1][0]);
        acc[1][1] = ffma2(xa.y, w1, acc[1][1]);
        acc[1][2] = ffma2(xa.y, w2, acc[1][2]);
        acc[1][3] = ffma2(xa.y, w3, acc[1][3]);
        acc[2][0] = ffma2(xb.x, w0, acc[2][0]);
        acc[2][1] = ffma2(xb.x, w1, acc[2][1]);
        acc[2][2] = ffma2(xb.x, w2, acc[2][2]);
        acc[2][3] = ffma2(xb.x, w3, acc[2][3]);
        acc[3][0] = ffma2(xb.y, w0, acc[3][0]);
        acc[3][1] = ffma2(xb.y, w1, acc[3][1]);
        acc[3][2] = ffma2(xb.y, w2, acc[3][2]);
        acc[3][3] = ffma2(xb.y, w3, acc[3][3]);
    }
}

__device__ __forceinline__ void init_bias(const float* __restrict__ sB,
                                          int j0, ull acc[4][4]) {
    ull bd[4];
    #pragma unroll
    for (int c = 0; c < 4; c++) bd[c] = dup2(sB[j0 + c]);
    #pragma unroll
    for (int p = 0; p < 4; p++)
        #pragma unroll
        for (int c = 0; c < 4; c++) acc[p][c] = bd[c];
}

// ---- branch B: pre1 = nf @ W1[0:128] + b1 (no dependency on aggregation) --
#define SM1_FLOATS (128 * XP + NODE_DIM * HID + HID)

__global__ void __launch_bounds__(256)
k_mlp1(const float* __restrict__ nf, const float* __restrict__ W1,
       const float* __restrict__ b1) {
    extern __shared__ float sm[];
    float* sXT = sm;
    float* sW  = sm + 128 * XP;
    float* sB  = sW + NODE_DIM * HID;
    int tid = threadIdx.x;
    int n0 = blockIdx.x * 128;

    for (int i = tid; i < NODE_DIM * HID; i += 256) sW[i] = W1[i];
    if (tid < HID) sB[tid] = b1[tid];
    for (int i = tid; i < 128 * NODE_DIM; i += 256) {
        int n = i >> 7, k = i & 127;
        int gn = n0 + n;
        sXT[k * XP + n] = (gn < N_NODES) ? __ldcs(&nf[(size_t)gn * NODE_DIM + k]) : 0.f;
    }
    __syncthreads();

    int cg = tid & 15, ng = tid >> 4;
    int j0 = cg * 4, nb = ng * 8;
    ull acc[4][4];
    init_bias(sB, j0, acc);
    gemm_acc<NODE_DIM>(sXT, sW, j0, nb, acc);

    #pragma unroll
    for (int p = 0; p < 4; p++) {
        float l0, h0, l1, h1, l2, h2, l3, h3;
        unpack2(acc[p][0], l0, h0); unpack2(acc[p][1], l1, h1);
        unpack2(acc[p][2], l2, h2); unpack2(acc[p][3], l3, h3);
        int nA = n0 + nb + 2 * p;
        float4 oA = make_float4(l0, l1, l2, l3);
        float4 oB = make_float4(h0, h1, h2, h3);
        *(float4*)(g_pre + (size_t)nA * HID + j0) = oA;        // padded buffer
        *(float4*)(g_pre + (size_t)(nA + 1) * HID + j0) = oB;
    }
}

// ---- join: += agg @ W1[128:176], relu, L2, L3, LayerNorm ------------------
#define SM2_FLOATS (HID * XP + EDGE_DIM * HID + 2 * HID * HID + 4 * HID)

__global__ void __launch_bounds__(256)
k_mlp2(const float* __restrict__ W1,
       const float* __restrict__ W2, const float* __restrict__ b2,
       const float* __restrict__ W3, const float* __restrict__ b3,
       const float* __restrict__ gamma, const float* __restrict__ beta,
       float* __restrict__ out) {
    extern __shared__ float sm[];
    float* sA   = sm;                       // 64 x 132 (first 48 rows: agg)
    float* sW1b = sm + HID * XP;            // 48 x 64
    float* sW2  = sW1b + EDGE_DIM * HID;    // 64 x 64
    float* sW3  = sW2 + HID * HID;          // 64 x 64
    float* sV   = sW3 + HID * HID;          // b2, b3, gamma, beta
    int tid = threadIdx.x;
    int n0 = blockIdx.x * 128;

    for (int i = tid; i < EDGE_DIM * HID; i += 256) sW1b[i] = W1[NODE_DIM * HID + i];
    for (int i = tid; i < HID * HID; i += 256) { sW2[i] = W2[i]; sW3[i] = W3[i]; }
    if (tid < HID) {
        sV[tid]           = b2[tid];
        sV[HID + tid]     = b3[tid];
        sV[2 * HID + tid] = gamma[tid];
        sV[3 * HID + tid] = beta[tid];
    }
    for (int i = tid; i < 128 * EDGE_DIM; i += 256) {
        int n = i / EDGE_DIM, c = i - n * EDGE_DIM;
        int gn = n0 + n;
        sA[c * XP + n] = (gn < N_NODES) ? g_agg[(size_t)gn * EDGE_DIM + c] : 0.f;
    }

    int cg = tid & 15, ng = tid >> 4;
    int j0 = cg * 4, nb = ng * 8;
    ull acc[4][4];

    // init from pre1 (coalesced: 16 lanes read consecutive 16B of a node row)
    #pragma unroll
    for (int p = 0; p < 4; p++) {
        int nA = n0 + nb + 2 * p;
        float4 qa = *(const float4*)(g_pre + (size_t)nA * HID + j0);
        float4 qb = *(const float4*)(g_pre + (size_t)(nA + 1) * HID + j0);
        acc[p][0] = pack2(qa.x, qb.x);
        acc[p][1] = pack2(qa.y, qb.y);
        acc[p][2] = pack2(qa.z, qb.z);
        acc[p][3] = pack2(qa.w, qb.w);
    }
    __syncthreads();

    // layer 1 (agg part) + relu -> sA
    gemm_acc<EDGE_DIM>(sA, sW1b, j0, nb, acc);
    __syncthreads();
    #pragma unroll
    for (int p = 0; p < 4; p++)
        #pragma unroll
        for (int c = 0; c < 4; c++) {
            float lo, hi; unpack2(acc[p][c], lo, hi);
            *(ull*)(sA + (j0 + c) * XP + nb + 2 * p) =
                pack2(fmaxf(lo, 0.f), fmaxf(hi, 0.f));
        }
    __syncthreads();

    // layer 2 + relu -> sA
    init_bias(sV, j0, acc);
    gemm_acc<HID>(sA, sW2, j0, nb, acc);
    __syncthreads();
    #pragma unroll
    for (int p = 0; p < 4; p++)
        #pragma unroll
        for (int c = 0; c < 4; c++) {
            float lo, hi; unpack2(acc[p][c], lo, hi);
            *(ull*)(sA + (j0 + c) * XP + nb + 2 * p) =
                pack2(fmaxf(lo, 0.f), fmaxf(hi, 0.f));
        }
    __syncthreads();

    // layer 3 + LayerNorm
    init_bias(sV + HID, j0, acc);
    gemm_acc<HID>(sA, sW3, j0, nb, acc);

    float gm[4], bt[4];
    #pragma unroll
    for (int c = 0; c < 4; c++) {
        gm[c] = sV[2 * HID + j0 + c];
        bt[c] = sV[3 * HID + j0 + c];
    }

    #pragma unroll
    for (int p = 0; p < 4; p++) {
        ull s = fadd2(fadd2(acc[p][0], acc[p][1]), fadd2(acc[p][2], acc[p][3]));
        #pragma unroll
        for (int m = 1; m < 16; m <<= 1)
            s = fadd2(s, __shfl_xor_sync(0xffffffffu, s, m));
        ull nmean = fmul2(s, dup2(-1.0f / 64.0f));
        ull d0 = fadd2(acc[p][0], nmean);
        ull d1 = fadd2(acc[p][1], nmean);
        ull d2 = fadd2(acc[p][2], nmean);
        ull d3 = fadd2(acc[p][3], nmean);
        ull q = fmul2(d0, d0);
        q = ffma2(d1, d1, q);
        q = ffma2(d2, d2, q);
        q = ffma2(d3, d3, q);
        #pragma unroll
        for (int m = 1; m < 16; m <<= 1)
            q = fadd2(q, __shfl_xor_sync(0xffffffffu, q, m));
        ull var = fmul2(q, dup2(1.0f / 64.0f));
        float vlo, vhi; unpack2(var, vlo, vhi);
        float rlo = rsqrtf(vlo + LN_EPS);
        float rhi = rsqrtf(vhi + LN_EPS);
        float l0, h0, l1, h1, l2, h2, l3, h3;
        unpack2(d0, l0, h0); unpack2(d1, l1, h1);
        unpack2(d2, l2, h2); unpack2(d3, l3, h3);
        int nA = n0 + nb + 2 * p, nB = nA + 1;
        if (nA < N_NODES) {
            float4 o;
            o.x = l0 * rlo * gm[0] + bt[0];
            o.y = l1 * rlo * gm[1] + bt[1];
            o.z = l2 * rlo * gm[2] + bt[2];
            o.w = l3 * rlo * gm[3] + bt[3];
            *(float4*)(out + (size_t)nA * HID + j0) = o;
        }
        if (nB < N_NODES) {
            float4 o;
            o.x = h0 * rhi * gm[0] + bt[0];
            o.y = h1 * rhi * gm[1] + bt[1];
            o.z = h2 * rhi * gm[2] + bt[2];
            o.w = h3 * rhi * gm[3] + bt[3];
            *(float4*)(out + (size_t)nB * HID + j0) = o;
        }
    }
}

// ---------------- launch: forked graph (branch B overlaps branch A) --------
extern "C" void kernel_launch(void* const* d_in, const int* in_sizes, int n_in,
                              void* d_out, int out_size) {
    const float* nf = 0;
    const float* ef = 0;
    const float* W1 = 0;
    const int* recv = 0;
    const float* mats[2] = {0, 0};
    const float* vecs[5] = {0, 0, 0, 0, 0};
    int mi = 0, vi = 0;
    for (int i = 0; i < n_in; i++) {
        int s = in_sizes[i];
        const void* p = d_in[i];
        if (s == N_NODES * NODE_DIM) nf = (const float*)p;
        else if (s == N_EDGES * EDGE_DIM) ef = (const float*)p;
        else if (s == N_EDGES) recv = (const int*)p;
        else if (s == IN_DIM * HID) W1 = (const float*)p;
        else if (s == HID * HID) { if (mi < 2) mats[mi++] = (const float*)p; }
        else if (s == HID) { if (vi < 5) vecs[vi++] = (const float*)p; }
    }
    float* out = (float*)d_out;

    cudaFuncSetAttribute(k_mlp1, cudaFuncAttributeMaxDynamicSharedMemorySize,
                         SM1_FLOATS * (int)sizeof(float));
    cudaFuncSetAttribute(k_mlp2, cudaFuncAttributeMaxDynamicSharedMemorySize,
                         SM2_FLOATS * (int)sizeof(float));

    cudaStream_t s2;
    cudaStreamCreateWithFlags(&s2, cudaStreamNonBlocking);
    cudaEvent_t evF, evB;
    cudaEventCreateWithFlags(&evF, cudaEventDisableTiming);
    cudaEventCreateWithFlags(&evB, cudaEventDisableTiming);

    // fork: branch B (node-feature GEMM) on s2
    cudaEventRecord(evF, 0);
    cudaStreamWaitEvent(s2, evF, 0);
    k_mlp1<<<(N_NODES + 127) / 128, 256, SM1_FLOATS * (int)sizeof(float), s2>>>(
        nf, W1, vecs[0]);
    cudaEventRecord(evB, s2);

    // branch A: CSR build + gather-mean on default stream
    k_zero<<<(N_NODES + 255) / 256, 256>>>();
    k_hist4<<<(N_EDGES / 4 + 255) / 256, 256>>>((const int4*)recv);
    k_offscan<<<SCAN_BLOCKS, 1024>>>();
    k_fill4<<<(N_EDGES / 4 + 255) / 256, 256>>>((const int4*)recv);
    k_gather<<<(N_NODES + 7) / 8, 256>>>(ef);

    // join
    cudaStreamWaitEvent(0, evB, 0);
    k_mlp2<<<(N_NODES + 127) / 128, 256, SM2_FLOATS * (int)sizeof(float)>>>(
        W1, mats[0], vecs[1], mats[1], vecs[2], vecs[3], vecs[4], out);
}

// round 3
// speedup vs baseline: 1.3171x; 1.0891x over previous
#include <cuda_runtime.h>

#define N_NODES 100000
#define N_EDGES 1600000
#define NODE_DIM 128
#define EDGE_DIM 48
#define IN_DIM 176
#define HID 64
#define LN_EPS 1e-5f
#define SCAN_BLOCKS 98
#define N_PAD 100352
#define XP 132

// ---------------- scratch (static device globals) --------------------------
__device__ int   g_deg[N_NODES];
__device__ int   g_off[N_NODES + 1];
__device__ int   g_cursor[N_NODES];
__device__ int   g_csr[N_EDGES];
__device__ int   g_scanA[SCAN_BLOCKS];
__device__ float g_pre[(size_t)N_PAD * HID];

typedef unsigned long long ull;

// ---------------- packed f32x2 helpers -------------------------------------
__device__ __forceinline__ ull ffma2(ull a, ull b, ull c) {
    ull d;
    asm("fma.rn.f32x2 %0, %1, %2, %3;" : "=l"(d) : "l"(a), "l"(b), "l"(c));
    return d;
}
__device__ __forceinline__ ull fadd2(ull a, ull b) {
    ull d;
    asm("add.rn.f32x2 %0, %1, %2;" : "=l"(d) : "l"(a), "l"(b));
    return d;
}
__device__ __forceinline__ ull fmul2(ull a, ull b) {
    ull d;
    asm("mul.rn.f32x2 %0, %1, %2;" : "=l"(d) : "l"(a), "l"(b));
    return d;
}
__device__ __forceinline__ ull dup2(float x) {
    ull d; unsigned u = __float_as_uint(x);
    asm("mov.b64 %0, {%1, %1};" : "=l"(d) : "r"(u));
    return d;
}
__device__ __forceinline__ ull pack2(float lo, float hi) {
    ull d;
    asm("mov.b64 %0, {%1, %2};" : "=l"(d)
        : "r"(__float_as_uint(lo)), "r"(__float_as_uint(hi)));
    return d;
}
__device__ __forceinline__ void unpack2(ull a, float& lo, float& hi) {
    unsigned l, h;
    asm("mov.b64 {%0, %1}, %2;" : "=r"(l), "=r"(h) : "l"(a));
    lo = __uint_as_float(l);
    hi = __uint_as_float(h);
}

// ---------------- CSR build ------------------------------------------------
__global__ void k_zero() {
    int i = blockIdx.x * blockDim.x + threadIdx.x;
    if (i < N_NODES) g_deg[i] = 0;
    if (i < SCAN_BLOCKS) g_scanA[i] = -1;
}

__global__ void k_hist4(const int4* __restrict__ recv4) {
    int i = blockIdx.x * blockDim.x + threadIdx.x;
    if (i < N_EDGES / 4) {
        int4 r = recv4[i];
        atomicAdd(&g_deg[r.x], 1);
        atomicAdd(&g_deg[r.y], 1);
        atomicAdd(&g_deg[r.z], 1);
        atomicAdd(&g_deg[r.w], 1);
    }
}

__global__ void k_offscan() {
    int tid = threadIdx.x;
    int i = blockIdx.x * 1024 + tid;
    int v = (i < N_NODES) ? g_deg[i] : 0;
    int lane = tid & 31, w = tid >> 5;
    int incl = v;
    #pragma unroll
    for (int o = 1; o < 32; o <<= 1) {
        int a = __shfl_up_sync(0xffffffffu, incl, o);
        if (lane >= o) incl += a;
    }
    __shared__ int wsum[32], woff[32], sAgg[SCAN_BLOCKS], sBase, sTotal;
    if (lane == 31) wsum[w] = incl;
    __syncthreads();
    if (w == 0) {
        int t = wsum[lane], ti = t;
        #pragma unroll
        for (int o = 1; o < 32; o <<= 1) {
            int a = __shfl_up_sync(0xffffffffu, ti, o);
            if (lane >= o) ti += a;
        }
        woff[lane] = ti - t;
        if (lane == 31) sTotal = ti;
    }
    __syncthreads();
    if (tid == 0)
        *((volatile int*)&g_scanA[blockIdx.x]) = sTotal;
    if (tid < SCAN_BLOCKS) {
        volatile int* p = (volatile int*)&g_scanA[tid];
        int a;
        while ((a = *p) == -1) { }
        sAgg[tid] = a;
    }
    __syncthreads();
    if (tid == 0) {
        int b = 0;
        for (int j = 0; j < blockIdx.x; j++) b += sAgg[j];
        sBase = b;
        if (blockIdx.x == 0) g_off[N_NODES] = N_EDGES;
    }
    __syncthreads();
    int excl = sBase + woff[w] + incl - v;
    if (i < N_NODES) { g_off[i] = excl; g_cursor[i] = excl; }
}

__global__ void k_fill4(const int4* __restrict__ recv4) {
    int i = blockIdx.x * blockDim.x + threadIdx.x;
    if (i < N_EDGES / 4) {
        int4 r = recv4[i];
        int e0 = i * 4;
        int p;
        p = atomicAdd(&g_cursor[r.x], 1); g_csr[p] = e0;
        p = atomicAdd(&g_cursor[r.y], 1); g_csr[p] = e0 + 1;
        p = atomicAdd(&g_cursor[r.z], 1); g_csr[p] = e0 + 2;
        p = atomicAdd(&g_cursor[r.w], 1); g_csr[p] = e0 + 3;
    }
}

// ---------------- MLP core pieces ------------------------------------------
template<int K>
__device__ __forceinline__ void gemm_acc(const float* __restrict__ sIn,
                                         const float* __restrict__ sW,
                                         int j0, int nb, ull acc[4][4]) {
    #pragma unroll 8
    for (int k = 0; k < K; k++) {
        const ulonglong2* xp = (const ulonglong2*)(sIn + k * XP + nb);
        ulonglong2 xa = xp[0];
        ulonglong2 xb = xp[1];
        float4 w = *(const float4*)(sW + k * HID + j0);
        ull w0 = dup2(w.x), w1 = dup2(w.y), w2 = dup2(w.z), w3 = dup2(w.w);
        acc[0][0] = ffma2(xa.x, w0, acc[0][0]);
        acc[0][1] = ffma2(xa.x, w1, acc[0][1]);
        acc[0][2] = ffma2(xa.x, w2, acc[0][2]);
        acc[0][3] = ffma2(xa.x, w3, acc[0][3]);
        acc[1][0] = ffma2(xa.y, w0, acc[1][0]);
        acc[1][1] = ffma2(xa.y, w1, acc[1][1]);
        acc[1][2] = ffma2(xa.y, w2, acc[1][2]);
        acc[1][3] = ffma2(xa.y, w3, acc[1][3]);
        acc[2][0] = ffma2(xb.x, w0, acc[2][0]);
        acc[2][1] = ffma2(xb.x, w1, acc[2][1]);
        acc[2][2] = ffma2(xb.x, w2, acc[2][2]);
        acc[2][3] = ffma2(xb.x, w3, acc[2][3]);
        acc[3][0] = ffma2(xb.y, w0, acc[3][0]);
        acc[3][1] = ffma2(xb.y, w1, acc[3][1]);
        acc[3][2] = ffma2(xb.y, w2, acc[3][2]);
        acc[3][3] = ffma2(xb.y, w3, acc[3][3]);
    }
}

__device__ __forceinline__ void init_bias(const float* __restrict__ sB,
                                          int j0, ull acc[4][4]) {
    ull bd[4];
    #pragma unroll
    for (int c = 0; c < 4; c++) bd[c] = dup2(sB[j0 + c]);
    #pragma unroll
    for (int p = 0; p < 4; p++)
        #pragma unroll
        for (int c = 0; c < 4; c++) acc[p][c] = bd[c];
}

// ---- branch B: pre1 = nf @ W1[0:128] + b1 ---------------------------------
#define SM1_FLOATS (128 * XP + NODE_DIM * HID + HID)

__global__ void __launch_bounds__(256)
k_mlp1(const float* __restrict__ nf, const float* __restrict__ W1,
       const float* __restrict__ b1) {
    extern __shared__ float sm[];
    float* sXT = sm;
    float* sW  = sm + 128 * XP;
    float* sB  = sW + NODE_DIM * HID;
    int tid = threadIdx.x;
    int n0 = blockIdx.x * 128;

    for (int i = tid; i < NODE_DIM * HID; i += 256) sW[i] = W1[i];
    if (tid < HID) sB[tid] = b1[tid];
    for (int i = tid; i < 128 * NODE_DIM; i += 256) {
        int n = i >> 7, k = i & 127;
        int gn = n0 + n;
        sXT[k * XP + n] = (gn < N_NODES) ? __ldcs(&nf[(size_t)gn * NODE_DIM + k]) : 0.f;
    }
    __syncthreads();

    int cg = tid & 15, ng = tid >> 4;
    int j0 = cg * 4, nb = ng * 8;
    ull acc[4][4];
    init_bias(sB, j0, acc);
    gemm_acc<NODE_DIM>(sXT, sW, j0, nb, acc);

    #pragma unroll
    for (int p = 0; p < 4; p++) {
        float l0, h0, l1, h1, l2, h2, l3, h3;
        unpack2(acc[p][0], l0, h0); unpack2(acc[p][1], l1, h1);
        unpack2(acc[p][2], l2, h2); unpack2(acc[p][3], l3, h3);
        int nA = n0 + nb + 2 * p;
        float4 oA = make_float4(l0, l1, l2, l3);
        float4 oB = make_float4(h0, h1, h2, h3);
        *(float4*)(g_pre + (size_t)nA * HID + j0) = oA;
        *(float4*)(g_pre + (size_t)(nA + 1) * HID + j0) = oB;
    }
}

// ---- fused join: gather-mean + agg GEMM + L2 + L3 + LayerNorm -------------
#define SM2_FLOATS (HID * XP + EDGE_DIM * HID + 2 * HID * HID + 4 * HID)

__global__ void __launch_bounds__(256, 2)
k_fused(const float* __restrict__ ef,
        const float* __restrict__ W1,
        const float* __restrict__ W2, const float* __restrict__ b2,
        const float* __restrict__ W3, const float* __restrict__ b3,
        const float* __restrict__ gamma, const float* __restrict__ beta,
        float* __restrict__ out) {
    extern __shared__ float sm[];
    float* sA   = sm;                       // 64 x XP; rows 0..47 = agg means
    float* sW1b = sm + HID * XP;
    float* sW2  = sW1b + EDGE_DIM * HID;
    float* sW3  = sW2 + HID * HID;
    float* sV   = sW3 + HID * HID;
    int tid = threadIdx.x;
    int n0 = blockIdx.x * 128;

    // stage weights first (quick, overlaps with gather loads below)
    for (int i = tid; i < EDGE_DIM * HID; i += 256) sW1b[i] = W1[NODE_DIM * HID + i];
    for (int i = tid; i < HID * HID; i += 256) { sW2[i] = W2[i]; sW3[i] = W3[i]; }
    if (tid < HID) {
        sV[tid]           = b2[tid];
        sV[HID + tid]     = b3[tid];
        sV[2 * HID + tid] = gamma[tid];
        sV[3 * HID + tid] = beta[tid];
    }

    // ---- gather-mean: 4 threads per node, direct smem stores, no shuffles
    int sub = tid & 3;
    const float4* ef4 = (const float4*)ef;
    #pragma unroll
    for (int pass = 0; pass < 2; pass++) {
        int nl = pass * 64 + (tid >> 2);
        int gn = n0 + nl;
        float4 a0 = make_float4(0.f, 0.f, 0.f, 0.f), a1 = a0, a2 = a0;
        if (gn < N_NODES) {
            int s = __ldg(&g_off[gn]), e = __ldg(&g_off[gn + 1]);
            for (int p = s; p < e; p++) {
                int eid = __ldg(&g_csr[p]);
                const float4* row = ef4 + (size_t)eid * 12 + sub * 3;
                float4 r0 = __ldcs(row), r1 = __ldcs(row + 1), r2 = __ldcs(row + 2);
                a0.x += r0.x; a0.y += r0.y; a0.z += r0.z; a0.w += r0.w;
                a1.x += r1.x; a1.y += r1.y; a1.z += r1.z; a1.w += r1.w;
                a2.x += r2.x; a2.y += r2.y; a2.z += r2.z; a2.w += r2.w;
            }
            int d = e - s;
            float sc = 1.0f / (float)(d > 0 ? d : 1);
            a0.x *= sc; a0.y *= sc; a0.z *= sc; a0.w *= sc;
            a1.x *= sc; a1.y *= sc; a1.z *= sc; a1.w *= sc;
            a2.x *= sc; a2.y *= sc; a2.z *= sc; a2.w *= sc;
        }
        float* col = sA + nl;
        int r0b = sub * 12;
        col[(r0b + 0) * XP] = a0.x;  col[(r0b + 1) * XP] = a0.y;
        col[(r0b + 2) * XP] = a0.z;  col[(r0b + 3) * XP] = a0.w;
        col[(r0b + 4) * XP] = a1.x;  col[(r0b + 5) * XP] = a1.y;
        col[(r0b + 6) * XP] = a1.z;  col[(r0b + 7) * XP] = a1.w;
        col[(r0b + 8) * XP] = a2.x;  col[(r0b + 9) * XP] = a2.y;
        col[(r0b + 10) * XP] = a2.z; col[(r0b + 11) * XP] = a2.w;
    }

    int cg = tid & 15, ng = tid >> 4;
    int j0 = cg * 4, nb = ng * 8;
    ull acc[4][4];

    // init acc from pre1 (nf @ W1a + b1), coalesced
    #pragma unroll
    for (int p = 0; p < 4; p++) {
        int nA = n0 + nb + 2 * p;
        float4 qa = *(const float4*)(g_pre + (size_t)nA * HID + j0);
        float4 qb = *(const float4*)(g_pre + (size_t)(nA + 1) * HID + j0);
        acc[p][0] = pack2(qa.x, qb.x);
        acc[p][1] = pack2(qa.y, qb.y);
        acc[p][2] = pack2(qa.z, qb.z);
        acc[p][3] = pack2(qa.w, qb.w);
    }
    __syncthreads();

    // layer 1 (agg part) + relu -> sA
    gemm_acc<EDGE_DIM>(sA, sW1b, j0, nb, acc);
    __syncthreads();
    #pragma unroll
    for (int p = 0; p < 4; p++)
        #pragma unroll
        for (int c = 0; c < 4; c++) {
            float lo, hi; unpack2(acc[p][c], lo, hi);
            *(ull*)(sA + (j0 + c) * XP + nb + 2 * p) =
                pack2(fmaxf(lo, 0.f), fmaxf(hi, 0.f));
        }
    __syncthreads();

    // layer 2 + relu -> sA
    init_bias(sV, j0, acc);
    gemm_acc<HID>(sA, sW2, j0, nb, acc);
    __syncthreads();
    #pragma unroll
    for (int p = 0; p < 4; p++)
        #pragma unroll
        for (int c = 0; c < 4; c++) {
            float lo, hi; unpack2(acc[p][c], lo, hi);
            *(ull*)(sA + (j0 + c) * XP + nb + 2 * p) =
                pack2(fmaxf(lo, 0.f), fmaxf(hi, 0.f));
        }
    __syncthreads();

    // layer 3 + LayerNorm
    init_bias(sV + HID, j0, acc);
    gemm_acc<HID>(sA, sW3, j0, nb, acc);

    float gm[4], bt[4];
    #pragma unroll
    for (int c = 0; c < 4; c++) {
        gm[c] = sV[2 * HID + j0 + c];
        bt[c] = sV[3 * HID + j0 + c];
    }

    #pragma unroll
    for (int p = 0; p < 4; p++) {
        ull s = fadd2(fadd2(acc[p][0], acc[p][1]), fadd2(acc[p][2], acc[p][3]));
        #pragma unroll
        for (int m = 1; m < 16; m <<= 1)
            s = fadd2(s, __shfl_xor_sync(0xffffffffu, s, m));
        ull nmean = fmul2(s, dup2(-1.0f / 64.0f));
        ull d0 = fadd2(acc[p][0], nmean);
        ull d1 = fadd2(acc[p][1], nmean);
        ull d2 = fadd2(acc[p][2], nmean);
        ull d3 = fadd2(acc[p][3], nmean);
        ull q = fmul2(d0, d0);
        q = ffma2(d1, d1, q);
        q = ffma2(d2, d2, q);
        q = ffma2(d3, d3, q);
        #pragma unroll
        for (int m = 1; m < 16; m <<= 1)
            q = fadd2(q, __shfl_xor_sync(0xffffffffu, q, m));
        ull var = fmul2(q, dup2(1.0f / 64.0f));
        float vlo, vhi; unpack2(var, vlo, vhi);
        float rlo = rsqrtf(vlo + LN_EPS);
        float rhi = rsqrtf(vhi + LN_EPS);
        float l0, h0, l1, h1, l2, h2, l3, h3;
        unpack2(d0, l0, h0); unpack2(d1, l1, h1);
        unpack2(d2, l2, h2); unpack2(d3, l3, h3);
        int nA = n0 + nb + 2 * p, nB = nA + 1;
        if (nA < N_NODES) {
            float4 o;
            o.x = l0 * rlo * gm[0] + bt[0];
            o.y = l1 * rlo * gm[1] + bt[1];
            o.z = l2 * rlo * gm[2] + bt[2];
            o.w = l3 * rlo * gm[3] + bt[3];
            *(float4*)(out + (size_t)nA * HID + j0) = o;
        }
        if (nB < N_NODES) {
            float4 o;
            o.x = h0 * rhi * gm[0] + bt[0];
            o.y = h1 * rhi * gm[1] + bt[1];
            o.z = h2 * rhi * gm[2] + bt[2];
            o.w = h3 * rhi * gm[3] + bt[3];
            *(float4*)(out + (size_t)nB * HID + j0) = o;
        }
    }
}

// ---------------- launch: forked graph -------------------------------------
extern "C" void kernel_launch(void* const* d_in, const int* in_sizes, int n_in,
                              void* d_out, int out_size) {
    const float* nf = 0;
    const float* ef = 0;
    const float* W1 = 0;
    const int* recv = 0;
    const float* mats[2] = {0, 0};
    const float* vecs[5] = {0, 0, 0, 0, 0};
    int mi = 0, vi = 0;
    for (int i = 0; i < n_in; i++) {
        int s = in_sizes[i];
        const void* p = d_in[i];
        if (s == N_NODES * NODE_DIM) nf = (const float*)p;
        else if (s == N_EDGES * EDGE_DIM) ef = (const float*)p;
        else if (s == N_EDGES) recv = (const int*)p;
        else if (s == IN_DIM * HID) W1 = (const float*)p;
        else if (s == HID * HID) { if (mi < 2) mats[mi++] = (const float*)p; }
        else if (s == HID) { if (vi < 5) vecs[vi++] = (const float*)p; }
    }
    float* out = (float*)d_out;

    cudaFuncSetAttribute(k_mlp1, cudaFuncAttributeMaxDynamicSharedMemorySize,
                         SM1_FLOATS * (int)sizeof(float));
    cudaFuncSetAttribute(k_fused, cudaFuncAttributeMaxDynamicSharedMemorySize,
                         SM2_FLOATS * (int)sizeof(float));

    cudaStream_t s2;
    cudaStreamCreateWithFlags(&s2, cudaStreamNonBlocking);
    cudaEvent_t evF, evB;
    cudaEventCreateWithFlags(&evF, cudaEventDisableTiming);
    cudaEventCreateWithFlags(&evB, cudaEventDisableTiming);

    // fork: branch B (node-feature GEMM) on s2
    cudaEventRecord(evF, 0);
    cudaStreamWaitEvent(s2, evF, 0);
    k_mlp1<<<(N_NODES + 127) / 128, 256, SM1_FLOATS * (int)sizeof(float), s2>>>(
        nf, W1, vecs[0]);
    cudaEventRecord(evB, s2);

    // branch A: CSR build on default stream
    k_zero<<<(N_NODES + 255) / 256, 256>>>();
    k_hist4<<<(N_EDGES / 4 + 255) / 256, 256>>>((const int4*)recv);
    k_offscan<<<SCAN_BLOCKS, 1024>>>();
    k_fill4<<<(N_EDGES / 4 + 255) / 256, 256>>>((const int4*)recv);

    // join: fused gather + MLP tail + LayerNorm
    cudaStreamWaitEvent(0, evB, 0);
    k_fused<<<(N_NODES + 127) / 128, 256, SM2_FLOATS * (int)sizeof(float)>>>(
        ef, W1, mats[0], vecs[1], mats[1], vecs[2], vecs[3], vecs[4], out);
}